// round 15
// baseline (speedup 1.0000x reference)
#include <cuda_runtime.h>
#include <cuda_fp16.h>
#include <math.h>
#include <stdint.h>

#define NN 50000
#define EE 1600000
#define ET (EE + NN)
#define FULLM 0xFFFFFFFFu

// ------------------- scratch (device globals; no allocation allowed) -------
__device__ __half g_h1h[NN * 64];
__device__ __half g_hm[NN * 64];
__device__ __half g_aggh[NN * 64];
__device__ float g_asrc1[NN * 8];
__device__ float g_adst1[NN * 8];
__device__ float g_asrc2[NN];
__device__ float g_adst2[NN];
__device__ int   g_counts[NN];
__device__ int   g_rowoff[NN + 1];
__device__ int   g_csrsrc[ET];
__device__ int   g_erank[EE];
__device__ int   g_blocksum[64];
__device__ float g_wsd[128];
// pre-transposed fp16 weights: Bt[n][k] = W[k][n]
__device__ __half g_B1[128 * 128];
__device__ __half g_B2[64 * 128];
__device__ __half g_B3[128 * 64];

__device__ __forceinline__ float leaky(float x) { return x > 0.f ? x : 0.2f * x; }

__device__ __forceinline__ uint32_t smem_u32(const void* p) {
    uint32_t a;
    asm("{ .reg .u64 t; cvta.to.shared.u64 t, %1; cvt.u32.u64 %0, t; }" : "=r"(a) : "l"(p));
    return a;
}
__device__ __forceinline__ void ldsm4(uint32_t* r, uint32_t addr) {
    asm volatile("ldmatrix.sync.aligned.m8n8.x4.shared.b16 {%0,%1,%2,%3}, [%4];"
        : "=r"(r[0]), "=r"(r[1]), "=r"(r[2]), "=r"(r[3]) : "r"(addr));
}
__device__ __forceinline__ void mma16816(float* d, const uint32_t* a, const uint32_t* b) {
    asm volatile(
        "mma.sync.aligned.m16n8k16.row.col.f32.f16.f16.f32 "
        "{%0,%1,%2,%3}, {%4,%5,%6,%7}, {%8,%9}, {%0,%1,%2,%3};"
        : "+f"(d[0]), "+f"(d[1]), "+f"(d[2]), "+f"(d[3])
        : "r"(a[0]), "r"(a[1]), "r"(a[2]), "r"(a[3]), "r"(b[0]), "r"(b[1]));
}

// ------------------- weight prep ---------------------------------------------
__global__ void prep_w_kernel(const float* __restrict__ Wm, const float* __restrict__ W1,
                              const float* __restrict__ W2,
                              const float* __restrict__ attS2, const float* __restrict__ attD2)
{
    int i = blockIdx.x * 256 + threadIdx.x;
    if (i < 16384)      { int n = i >> 7, k = i & 127; g_B1[i] = __float2half(Wm[k * 128 + n]); }
    else if (i < 24576) { int j = i - 16384; int n = j >> 7, k = j & 127; g_B2[j] = __float2half(W1[k * 64 + n]); }
    else if (i < 32768) { int j = i - 24576; int n = j >> 6, k = j & 63;  g_B3[j] = __float2half(W2[k * 128 + n]); }
    else if (i < 32832) {
        int k = i - 32768;
        float s = 0.f, d = 0.f;
        const float* row = W2 + k * 128;
#pragma unroll 4
        for (int n = 0; n < 128; n++) {
            s = fmaf(row[n], attS2[n], s);
            d = fmaf(row[n], attD2[n], d);
        }
        g_wsd[k] = s;
        g_wsd[64 + k] = d;
    }
}

// ------------------- fused GEMM1+GEMM2 (+att1) --------------------------------
__global__ void __launch_bounds__(256, 2) gemm12_kernel(
    const float* __restrict__ A32,
    const float* __restrict__ bias,
    const float* __restrict__ attS, const float* __restrict__ attD,
    __half* __restrict__ outh1,
    float* __restrict__ asrc, float* __restrict__ adst,
    int M)
{
    constexpr int LDA = 136;
    const int tid = threadIdx.x;
    const int warp = tid >> 5;
    const int lane = tid & 31;
    const int gid = lane >> 2;
    const int tig = lane & 3;
    const int row0 = blockIdx.x * 128;
    const int WM = (warp & 3) * 32;
    const int WN1 = (warp >> 2) * 64;
    const int WN2 = (warp >> 2) * 32;

    extern __shared__ char sm[];
    __half* sA  = (__half*)sm;
    __half* sB1 = sA + 128 * LDA;
    __half* sB2 = sB1 + 128 * LDA;
    float* sBias = (float*)(sB2 + 64 * LDA);
    float* sAS = sBias + 128;
    float* sAD = sAS + 64;

    for (int idx = tid; idx < 128 * 32; idx += 256) {
        int r = idx >> 5;
        int c = (idx & 31) * 4;
        int gr = row0 + r;
        float4 v = make_float4(0.f, 0.f, 0.f, 0.f);
        if (gr < M) v = *(const float4*)(A32 + (size_t)gr * 128 + c);
        __half2 p0 = __floats2half2_rn(v.x, v.y);
        __half2 p1 = __floats2half2_rn(v.z, v.w);
        *(uint2*)(sA + r * LDA + c) = make_uint2(*(uint32_t*)&p0, *(uint32_t*)&p1);
    }
    for (int idx = tid; idx < 128 * 16; idx += 256) {
        int n = idx >> 4;
        int c = (idx & 15) * 8;
        *(uint4*)(sB1 + n * LDA + c) = *(const uint4*)(g_B1 + n * 128 + c);
    }
    for (int idx = tid; idx < 64 * 16; idx += 256) {
        int n = idx >> 4;
        int c = (idx & 15) * 8;
        *(uint4*)(sB2 + n * LDA + c) = *(const uint4*)(g_B2 + n * 128 + c);
    }
    if (tid < 128) sBias[tid] = bias[tid];
    if (tid < 64) { sAS[tid] = attS[tid]; sAD[tid] = attD[tid]; }
    __syncthreads();

    const uint32_t uA = smem_u32(sA), uB1 = smem_u32(sB1), uB2 = smem_u32(sB2);
    const int a0off = (WM + (lane & 15)) * LDA + (lane >> 4) * 8;
    const int a1off = a0off + 16 * LDA;
    const int brow = lane & 7;
    const int bhalf = (lane >> 3) & 1;
    const int bsel = (lane >> 4) * 8 + brow;

    float acc[2][8][4];
#pragma unroll
    for (int m = 0; m < 2; m++)
#pragma unroll
        for (int t = 0; t < 8; t++)
#pragma unroll
            for (int j = 0; j < 4; j++) acc[m][t][j] = 0.f;

#pragma unroll
    for (int ks = 0; ks < 8; ks++) {
        uint32_t a0[4], a1[4];
        ldsm4(a0, uA + (uint32_t)(a0off + ks * 16) * 2);
        ldsm4(a1, uA + (uint32_t)(a1off + ks * 16) * 2);
#pragma unroll
        for (int p = 0; p < 4; p++) {
            int boff = (WN1 + p * 16 + bsel) * LDA + ks * 16 + bhalf * 8;
            uint32_t b[4];
            ldsm4(b, uB1 + (uint32_t)boff * 2);
            mma16816(acc[0][2 * p],     a0, b);
            mma16816(acc[0][2 * p + 1], a0, b + 2);
            mma16816(acc[1][2 * p],     a1, b);
            mma16816(acc[1][2 * p + 1], a1, b + 2);
        }
    }
    __syncthreads();

#pragma unroll
    for (int m = 0; m < 2; m++) {
        int lr0 = WM + m * 16 + gid;
        int lr1 = lr0 + 8;
#pragma unroll
        for (int t = 0; t < 8; t++) {
            int c = WN1 + t * 8 + tig * 2;
            __half2 p0 = __floats2half2_rn(acc[m][t][0] + sBias[c], acc[m][t][1] + sBias[c + 1]);
            __half2 p1 = __floats2half2_rn(acc[m][t][2] + sBias[c], acc[m][t][3] + sBias[c + 1]);
            *(uint32_t*)(sA + lr0 * LDA + c) = *(uint32_t*)&p0;
            *(uint32_t*)(sA + lr1 * LDA + c) = *(uint32_t*)&p1;
        }
    }
    __syncthreads();

    float acc2[2][4][4];
#pragma unroll
    for (int m = 0; m < 2; m++)
#pragma unroll
        for (int t = 0; t < 4; t++)
#pragma unroll
            for (int j = 0; j < 4; j++) acc2[m][t][j] = 0.f;

#pragma unroll
    for (int ks = 0; ks < 8; ks++) {
        uint32_t a0[4], a1[4];
        ldsm4(a0, uA + (uint32_t)(a0off + ks * 16) * 2);
        ldsm4(a1, uA + (uint32_t)(a1off + ks * 16) * 2);
#pragma unroll
        for (int p = 0; p < 2; p++) {
            int boff = (WN2 + p * 16 + bsel) * LDA + ks * 16 + bhalf * 8;
            uint32_t b[4];
            ldsm4(b, uB2 + (uint32_t)boff * 2);
            mma16816(acc2[0][2 * p],     a0, b);
            mma16816(acc2[0][2 * p + 1], a0, b + 2);
            mma16816(acc2[1][2 * p],     a1, b);
            mma16816(acc2[1][2 * p + 1], a1, b + 2);
        }
    }

#pragma unroll
    for (int m = 0; m < 2; m++) {
        int r0 = row0 + WM + m * 16 + gid;
        int r1 = r0 + 8;
#pragma unroll
        for (int t = 0; t < 4; t++) {
            int c = WN2 + t * 8 + tig * 2;
            int head = (WN2 >> 3) + t;
            float sl  = acc2[m][t][0] * sAS[c] + acc2[m][t][1] * sAS[c + 1];
            float shh = acc2[m][t][2] * sAS[c] + acc2[m][t][3] * sAS[c + 1];
            float dl  = acc2[m][t][0] * sAD[c] + acc2[m][t][1] * sAD[c + 1];
            float dhh = acc2[m][t][2] * sAD[c] + acc2[m][t][3] * sAD[c + 1];
#pragma unroll
            for (int o = 1; o < 4; o <<= 1) {
                sl  += __shfl_xor_sync(FULLM, sl, o);
                shh += __shfl_xor_sync(FULLM, shh, o);
                dl  += __shfl_xor_sync(FULLM, dl, o);
                dhh += __shfl_xor_sync(FULLM, dhh, o);
            }
            if (tig == 0) {
                if (r0 < M) { asrc[(size_t)r0 * 8 + head] = sl;  adst[(size_t)r0 * 8 + head] = dl; }
                if (r1 < M) { asrc[(size_t)r1 * 8 + head] = shh; adst[(size_t)r1 * 8 + head] = dhh; }
            }
            __half2 p0 = __floats2half2_rn(acc2[m][t][0], acc2[m][t][1]);
            __half2 p1 = __floats2half2_rn(acc2[m][t][2], acc2[m][t][3]);
            if (r0 < M) *(uint32_t*)(outh1 + (size_t)r0 * 64 + c) = *(uint32_t*)&p0;
            if (r1 < M) *(uint32_t*)(outh1 + (size_t)r1 * 64 + c) = *(uint32_t*)&p1;
        }
    }
}
#define SMEM_G12 ((128 + 128 + 64) * 136 * 2 + 128 * 4 + 64 * 8 + 256)

// ------------------- GEMM3: out = aggh @ W2 + b2 ------------------------------
__global__ void __launch_bounds__(256) gemm3_kernel(
    const __half* __restrict__ Ag,
    const float* __restrict__ bias,
    float* __restrict__ out,
    int M)
{
    constexpr int K = 64, NC = 128, LDA = 72;
    const int tid = threadIdx.x;
    const int warp = tid >> 5;
    const int lane = tid & 31;
    const int gid = lane >> 2;
    const int tig = lane & 3;
    const int row0 = blockIdx.x * 128;
    const int WM = (warp & 3) * 32;
    const int WN = (warp >> 2) * 64;

    extern __shared__ char sm[];
    __half* sA = (__half*)sm;
    __half* sB = sA + 128 * LDA;
    float* sBias = (float*)(sB + NC * LDA);

    for (int idx = tid; idx < 128 * (K / 8); idx += 256) {
        int r = idx / (K / 8);
        int c = (idx % (K / 8)) * 8;
        int gr = row0 + r;
        uint4 v = make_uint4(0, 0, 0, 0);
        if (gr < M) v = *(const uint4*)(Ag + (size_t)gr * K + c);
        *(uint4*)(sA + r * LDA + c) = v;
    }
    for (int idx = tid; idx < NC * (K / 8); idx += 256) {
        int n = idx / (K / 8);
        int c = (idx % (K / 8)) * 8;
        *(uint4*)(sB + n * LDA + c) = *(const uint4*)(g_B3 + n * K + c);
    }
    if (tid < NC) sBias[tid] = bias[tid];
    __syncthreads();

    float acc[2][8][4];
#pragma unroll
    for (int m = 0; m < 2; m++)
#pragma unroll
        for (int t = 0; t < 8; t++)
#pragma unroll
            for (int j = 0; j < 4; j++) acc[m][t][j] = 0.f;

    const uint32_t uA = smem_u32(sA), uB = smem_u32(sB);
    const int a0off = (WM + (lane & 15)) * LDA + (lane >> 4) * 8;
    const int a1off = a0off + 16 * LDA;
    const int brow = lane & 7;
    const int bhalf = (lane >> 3) & 1;
    const int bsel = (lane >> 4) * 8 + brow;

#pragma unroll
    for (int ks = 0; ks < K / 16; ks++) {
        uint32_t a0[4], a1[4];
        ldsm4(a0, uA + (uint32_t)(a0off + ks * 16) * 2);
        ldsm4(a1, uA + (uint32_t)(a1off + ks * 16) * 2);
#pragma unroll
        for (int p = 0; p < 4; p++) {
            int boff = (WN + p * 16 + bsel) * LDA + ks * 16 + bhalf * 8;
            uint32_t b[4];
            ldsm4(b, uB + (uint32_t)boff * 2);
            mma16816(acc[0][2 * p],     a0, b);
            mma16816(acc[0][2 * p + 1], a0, b + 2);
            mma16816(acc[1][2 * p],     a1, b);
            mma16816(acc[1][2 * p + 1], a1, b + 2);
        }
    }

#pragma unroll
    for (int m = 0; m < 2; m++) {
        int r0 = row0 + WM + m * 16 + gid;
        int r1 = r0 + 8;
#pragma unroll
        for (int t = 0; t < 8; t++) {
            int c = WN + t * 8 + tig * 2;
            float b0 = sBias[c], b1v = sBias[c + 1];
            if (r0 < M) {
                float2 v = make_float2(acc[m][t][0] + b0, acc[m][t][1] + b1v);
                *(float2*)(out + (size_t)r0 * NC + c) = v;
            }
            if (r1 < M) {
                float2 v = make_float2(acc[m][t][2] + b0, acc[m][t][3] + b1v);
                *(float2*)(out + (size_t)r1 * NC + c) = v;
            }
        }
    }
}
#define SMEM_G3 ((128 + 128) * 72 * 2 + 128 * 4 + 256)

// ------------------- static init ---------------------------------------------
struct HxInit {
    cudaStream_t s2;
    cudaEvent_t evF, evJ;
    HxInit() {
        cudaStreamCreateWithFlags(&s2, cudaStreamNonBlocking);
        cudaEventCreateWithFlags(&evF, cudaEventDisableTiming);
        cudaEventCreateWithFlags(&evJ, cudaEventDisableTiming);
        cudaFuncSetAttribute(gemm12_kernel, cudaFuncAttributeMaxDynamicSharedMemorySize, SMEM_G12);
        cudaFuncSetAttribute(gemm3_kernel,  cudaFuncAttributeMaxDynamicSharedMemorySize, SMEM_G3);
    }
};
static HxInit g_hx;

// ------------------- CSR build (proven 3-kernel scan + rank scatter) ---------
__global__ void init_kernel()
{
    int i = blockIdx.x * 256 + threadIdx.x;
    if (i < NN) g_counts[i] = 1;   // slot 0 reserved for self loop
}

__global__ void count_kernel(const int* __restrict__ dst)
{
    int e = blockIdx.x * 256 + threadIdx.x;
    if (e < EE) g_erank[e] = atomicAdd(&g_counts[dst[e]], 1);
}

__global__ void __launch_bounds__(1024) scan1_kernel()
{
    __shared__ int wsum[32];
    int tid = threadIdx.x, lane = tid & 31, wid = tid >> 5;
    int idx = blockIdx.x * 1024 + tid;
    int v = (idx < NN) ? g_counts[idx] : 0;
    int x = v;
#pragma unroll
    for (int off = 1; off < 32; off <<= 1) {
        int y = __shfl_up_sync(FULLM, x, off);
        if (lane >= off) x += y;
    }
    if (lane == 31) wsum[wid] = x;
    __syncthreads();
    if (wid == 0) {
        int wv = wsum[lane];
#pragma unroll
        for (int off = 1; off < 32; off <<= 1) {
            int y = __shfl_up_sync(FULLM, wv, off);
            if (lane >= off) wv += y;
        }
        wsum[lane] = wv;
    }
    __syncthreads();
    int pre = (wid > 0) ? wsum[wid - 1] : 0;
    if (idx < NN) g_rowoff[idx] = x + pre - v;
    if (tid == 1023) g_blocksum[blockIdx.x] = x + pre;
}

__global__ void __launch_bounds__(64) scan2_kernel(int nblocks)
{
    __shared__ int s0tot;
    int tid = threadIdx.x, lane = tid & 31, wid = tid >> 5;
    int v = (tid < nblocks) ? g_blocksum[tid] : 0;
    int x = v;
#pragma unroll
    for (int off = 1; off < 32; off <<= 1) {
        int y = __shfl_up_sync(FULLM, x, off);
        if (lane >= off) x += y;
    }
    if (wid == 0 && lane == 31) s0tot = x;
    __syncthreads();
    int pre = (wid == 1) ? s0tot : 0;
    int excl = x - v + pre;
    if (tid < nblocks) g_blocksum[tid] = excl;
    if (tid == nblocks - 1) g_rowoff[NN] = excl + v;
}

__global__ void __launch_bounds__(1024) scan3_kernel()
{
    int idx = blockIdx.x * 1024 + threadIdx.x;
    if (idx < NN) {
        int off = g_rowoff[idx] + g_blocksum[blockIdx.x];
        g_rowoff[idx] = off;
        g_csrsrc[off] = idx;    // self loop
    }
}

__global__ void scatter_kernel(const int* __restrict__ src, const int* __restrict__ dst)
{
    int e = blockIdx.x * 256 + threadIdx.x;
    if (e < EE) {
        int d = dst[e];
        g_csrsrc[g_rowoff[d] + g_erank[e]] = src[e];
    }
}

// ------------------- GAT conv1 aggregation (lane-parallel weights) -----------
__global__ void __launch_bounds__(256) agg1_kernel(const float* __restrict__ b1)
{
    int w = (blockIdx.x * blockDim.x + threadIdx.x) >> 5;
    int lane = threadIdx.x & 31;
    if (w >= NN) return;
    int head = lane >> 2;
    int c0 = lane * 2;
    int beg = g_rowoff[w], end = g_rowoff[w + 1];

    float ad8 = g_adst1[w * 8 + (lane & 7)];
    float adh = __shfl_sync(FULLM, ad8, head);

    float a0 = 0.f, a1 = 0.f, sSum = 0.f;
    float b0a = 0.f, b1a = 0.f;
    float c0a = 0.f, c1a = 0.f;
    float d0a = 0.f, d1a = 0.f;

    for (int base = beg; base < end; base += 32) {
        int n = end - base;
        int kmax = n < 32 ? n : 32;
        int sl = (lane < kmax) ? g_csrsrc[base + lane] : 0;
        int k = 0;
        for (; k + 4 <= kmax; k += 4) {
            int sj = __shfl_sync(FULLM, sl, k + (lane >> 3));
            float e4 = __expf(leaky(g_asrc1[sj * 8 + (lane & 7)] + ad8));
            int s0 = __shfl_sync(FULLM, sl, k);
            int s1 = __shfl_sync(FULLM, sl, k + 1);
            int s2 = __shfl_sync(FULLM, sl, k + 2);
            int s3 = __shfl_sync(FULLM, sl, k + 3);
            float e0 = __shfl_sync(FULLM, e4, head);
            float e1 = __shfl_sync(FULLM, e4, 8 + head);
            float e2 = __shfl_sync(FULLM, e4, 16 + head);
            float e3 = __shfl_sync(FULLM, e4, 24 + head);
            float2 h0 = __half22float2(*(const __half2*)(g_h1h + s0 * 64 + c0));
            float2 h1 = __half22float2(*(const __half2*)(g_h1h + s1 * 64 + c0));
            float2 h2 = __half22float2(*(const __half2*)(g_h1h + s2 * 64 + c0));
            float2 h3 = __half22float2(*(const __half2*)(g_h1h + s3 * 64 + c0));
            a0 = fmaf(e0, h0.x, a0);  a1 = fmaf(e0, h0.y, a1);
            b0a = fmaf(e1, h1.x, b0a); b1a = fmaf(e1, h1.y, b1a);
            c0a = fmaf(e2, h2.x, c0a); c1a = fmaf(e2, h2.y, c1a);
            d0a = fmaf(e3, h3.x, d0a); d1a = fmaf(e3, h3.y, d1a);
            sSum += e0 + e1 + e2 + e3;
        }
        for (; k < kmax; k++) {
            int s = __shfl_sync(FULLM, sl, k);
            float e = __expf(leaky(g_asrc1[s * 8 + head] + adh));
            float2 hv = __half22float2(*(const __half2*)(g_h1h + s * 64 + c0));
            a0 = fmaf(e, hv.x, a0); a1 = fmaf(e, hv.y, a1);
            sSum += e;
        }
    }
    a0 += b0a + c0a + d0a;
    a1 += b1a + c1a + d1a;
    float inv = 1.f / sSum;
    float o0 = a0 * inv + b1[c0];
    float o1 = a1 * inv + b1[c0 + 1];
    o0 = o0 > 0.f ? o0 : expm1f(o0);
    o1 = o1 > 0.f ? o1 : expm1f(o1);
    __half2 p = __floats2half2_rn(o0, o1);
    *(uint32_t*)(g_hm + w * 64 + c0) = *(uint32_t*)&p;

    float ps = o0 * g_wsd[c0] + o1 * g_wsd[c0 + 1];
    float pd = o0 * g_wsd[64 + c0] + o1 * g_wsd[64 + c0 + 1];
#pragma unroll
    for (int off = 16; off; off >>= 1) {
        ps += __shfl_xor_sync(FULLM, ps, off);
        pd += __shfl_xor_sync(FULLM, pd, off);
    }
    if (lane == 0) { g_asrc2[w] = ps; g_adst2[w] = pd; }
}

// ------------------- GAT conv2 aggregation (8-wide staged consume) -----------
__global__ void __launch_bounds__(256) agg2_kernel()
{
    int w = (blockIdx.x * blockDim.x + threadIdx.x) >> 5;
    int lane = threadIdx.x & 31;
    if (w >= NN) return;
    int c0 = lane * 2;
    int beg = g_rowoff[w], end = g_rowoff[w + 1];
    float adh = g_adst2[w];

    float a0 = 0.f, a1 = 0.f, sSum = 0.f;
    float b0a = 0.f, b1a = 0.f;
    float c0a = 0.f, c1a = 0.f;
    float d0a = 0.f, d1a = 0.f;
    float e0a = 0.f, e1a = 0.f;
    float f0a = 0.f, f1a = 0.f;
    float g0a = 0.f, g1a = 0.f;
    float h0a = 0.f, h1a = 0.f;

    for (int base = beg; base < end; base += 32) {
        int n = end - base;
        int kmax = n < 32 ? n : 32;
        int sl = 0;
        float el = 0.f;
        if (lane < kmax) {
            sl = g_csrsrc[base + lane];
            el = __expf(leaky(g_asrc2[sl] + adh));
        }
        sSum += el;
        int k = 0;
        for (; k + 8 <= kmax; k += 8) {
            int s0 = __shfl_sync(FULLM, sl, k);
            int s1 = __shfl_sync(FULLM, sl, k + 1);
            int s2 = __shfl_sync(FULLM, sl, k + 2);
            int s3 = __shfl_sync(FULLM, sl, k + 3);
            int s4 = __shfl_sync(FULLM, sl, k + 4);
            int s5 = __shfl_sync(FULLM, sl, k + 5);
            int s6 = __shfl_sync(FULLM, sl, k + 6);
            int s7 = __shfl_sync(FULLM, sl, k + 7);
            float e0 = __shfl_sync(FULLM, el, k);
            float e1 = __shfl_sync(FULLM, el, k + 1);
            float e2 = __shfl_sync(FULLM, el, k + 2);
            float e3 = __shfl_sync(FULLM, el, k + 3);
            float e4 = __shfl_sync(FULLM, el, k + 4);
            float e5 = __shfl_sync(FULLM, el, k + 5);
            float e6 = __shfl_sync(FULLM, el, k + 6);
            float e7 = __shfl_sync(FULLM, el, k + 7);
            float2 h0 = __half22float2(*(const __half2*)(g_hm + s0 * 64 + c0));
            float2 h1 = __half22float2(*(const __half2*)(g_hm + s1 * 64 + c0));
            float2 h2 = __half22float2(*(const __half2*)(g_hm + s2 * 64 + c0));
            float2 h3 = __half22float2(*(const __half2*)(g_hm + s3 * 64 + c0));
            float2 h4 = __half22float2(*(const __half2*)(g_hm + s4 * 64 + c0));
            float2 h5 = __half22float2(*(const __half2*)(g_hm + s5 * 64 + c0));
            float2 h6 = __half22float2(*(const __half2*)(g_hm + s6 * 64 + c0));
            float2 h7 = __half22float2(*(const __half2*)(g_hm + s7 * 64 + c0));
            a0 = fmaf(e0, h0.x, a0);   a1 = fmaf(e0, h0.y, a1);
            b0a = fmaf(e1, h1.x, b0a); b1a = fmaf(e1, h1.y, b1a);
            c0a = fmaf(e2, h2.x, c0a); c1a = fmaf(e2, h2.y, c1a);
            d0a = fmaf(e3, h3.x, d0a); d1a = fmaf(e3, h3.y, d1a);
            e0a = fmaf(e4, h4.x, e0a); e1a = fmaf(e4, h4.y, e1a);
            f0a = fmaf(e5, h5.x, f0a); f1a = fmaf(e5, h5.y, f1a);
            g0a = fmaf(e6, h6.x, g0a); g1a = fmaf(e6, h6.y, g1a);
            h0a = fmaf(e7, h7.x, h0a); h1a = fmaf(e7, h7.y, h1a);
        }
        for (; k + 4 <= kmax; k += 4) {
            int s0 = __shfl_sync(FULLM, sl, k);
            int s1 = __shfl_sync(FULLM, sl, k + 1);
            int s2 = __shfl_sync(FULLM, sl, k + 2);
            int s3 = __shfl_sync(FULLM, sl, k + 3);
            float e0 = __shfl_sync(FULLM, el, k);
            float e1 = __shfl_sync(FULLM, el, k + 1);
            float e2 = __shfl_sync(FULLM, el, k + 2);
            float e3 = __shfl_sync(FULLM, el, k + 3);
            float2 h0 = __half22float2(*(const __half2*)(g_hm + s0 * 64 + c0));
            float2 h1 = __half22float2(*(const __half2*)(g_hm + s1 * 64 + c0));
            float2 h2 = __half22float2(*(const __half2*)(g_hm + s2 * 64 + c0));
            float2 h3 = __half22float2(*(const __half2*)(g_hm + s3 * 64 + c0));
            a0 = fmaf(e0, h0.x, a0);   a1 = fmaf(e0, h0.y, a1);
            b0a = fmaf(e1, h1.x, b0a); b1a = fmaf(e1, h1.y, b1a);
            c0a = fmaf(e2, h2.x, c0a); c1a = fmaf(e2, h2.y, c1a);
            d0a = fmaf(e3, h3.x, d0a); d1a = fmaf(e3, h3.y, d1a);
        }
        for (; k < kmax; k++) {
            int s = __shfl_sync(FULLM, sl, k);
            float e = __shfl_sync(FULLM, el, k);
            float2 hv = __half22float2(*(const __half2*)(g_hm + s * 64 + c0));
            a0 = fmaf(e, hv.x, a0); a1 = fmaf(e, hv.y, a1);
        }
    }
    a0 += b0a + c0a + d0a + e0a + f0a + g0a + h0a;
    a1 += b1a + c1a + d1a + e1a + f1a + g1a + h1a;
#pragma unroll
    for (int off = 16; off; off >>= 1)
        sSum += __shfl_xor_sync(FULLM, sSum, off);
    float inv = 1.f / sSum;
    __half2 p = __floats2half2_rn(a0 * inv, a1 * inv);
    *(uint32_t*)(g_aggh + w * 64 + c0) = *(uint32_t*)&p;
}

// ------------------- launch --------------------------------------------------
extern "C" void kernel_launch(void* const* d_in, const int* in_sizes, int n_in,
                              void* d_out, int out_size)
{
    (void)in_sizes; (void)n_in; (void)out_size;
    const float* x        = (const float*)d_in[0];
    const int*   ei       = (const int*)d_in[1];
    const float* W_map    = (const float*)d_in[2];
    const float* b_map    = (const float*)d_in[3];
    const float* W1       = (const float*)d_in[4];
    const float* att_src1 = (const float*)d_in[5];
    const float* att_dst1 = (const float*)d_in[6];
    const float* b1       = (const float*)d_in[7];
    const float* W2       = (const float*)d_in[8];
    const float* att_src2 = (const float*)d_in[9];
    const float* att_dst2 = (const float*)d_in[10];
    const float* b2       = (const float*)d_in[11];
    float* out = (float*)d_out;
    const int* src = ei;
    const int* dst = ei + EE;

    __half *p_h1h, *p_aggh;
    float *p_as1, *p_ad1;
    cudaGetSymbolAddress((void**)&p_h1h, g_h1h);
    cudaGetSymbolAddress((void**)&p_aggh, g_aggh);
    cudaGetSymbolAddress((void**)&p_as1, g_asrc1);
    cudaGetSymbolAddress((void**)&p_ad1, g_adst1);

    const int GEMM_BLOCKS = (NN + 127) / 128;
    const int N_BLOCKS    = (NN + 255) / 256;
    const int E_BLOCKS    = (EE + 255) / 256;
    const int WARP_BLOCKS = NN / 8;
    const int SCAN_BLOCKS = (NN + 1023) / 1024;

    cudaStream_t s2 = g_hx.s2;

    // fork FIRST: CSR arm starts immediately, prep_w only blocks the gemm arm
    cudaEventRecord(g_hx.evF, 0);
    cudaStreamWaitEvent(s2, g_hx.evF, 0);
    init_kernel<<<N_BLOCKS, 256, 0, s2>>>();
    count_kernel<<<E_BLOCKS, 256, 0, s2>>>(dst);

    prep_w_kernel<<<129, 256>>>(W_map, W1, W2, att_src2, att_dst2);
    gemm12_kernel<<<GEMM_BLOCKS, 256, SMEM_G12>>>(
        x, b_map, att_src1, att_dst1, p_h1h, p_as1, p_ad1, NN);

    scan1_kernel<<<SCAN_BLOCKS, 1024, 0, s2>>>();
    scan2_kernel<<<1, 64, 0, s2>>>(SCAN_BLOCKS);
    scan3_kernel<<<SCAN_BLOCKS, 1024, 0, s2>>>();
    scatter_kernel<<<E_BLOCKS, 256, 0, s2>>>(src, dst);
    cudaEventRecord(g_hx.evJ, s2);

    cudaStreamWaitEvent(0, g_hx.evJ, 0);

    agg1_kernel<<<WARP_BLOCKS, 256>>>(b1);
    agg2_kernel<<<WARP_BLOCKS, 256>>>();
    gemm3_kernel<<<GEMM_BLOCKS, 256, SMEM_G3>>>(p_aggh, b2, out, NN);
}

// round 16
// speedup vs baseline: 1.0224x; 1.0224x over previous
#include <cuda_runtime.h>
#include <cuda_fp16.h>
#include <math.h>
#include <stdint.h>

#define NN 50000
#define EE 1600000
#define ET (EE + NN)
#define FULLM 0xFFFFFFFFu

// ------------------- scratch (device globals; no allocation allowed) -------
__device__ __half g_h1h[NN * 64];
__device__ __half g_hm[NN * 64];
__device__ __half g_aggh[NN * 64];
__device__ float g_asrc1[NN * 8];
__device__ float g_adst1[NN * 8];
__device__ float g_asrc2[NN];
__device__ float g_adst2[NN];
__device__ int   g_counts[NN];
__device__ int   g_rowoff[NN + 1];
__device__ int   g_csrsrc[ET];
__device__ int   g_erank[EE];
__device__ int   g_blocksum[64];
__device__ float g_wsd[128];
// pre-transposed fp16 weights: Bt[n][k] = W[k][n]
__device__ __half g_B1[128 * 128];
__device__ __half g_B2[64 * 128];
__device__ __half g_B3[128 * 64];

__device__ __forceinline__ float leaky(float x) { return x > 0.f ? x : 0.2f * x; }

__device__ __forceinline__ uint32_t smem_u32(const void* p) {
    uint32_t a;
    asm("{ .reg .u64 t; cvta.to.shared.u64 t, %1; cvt.u32.u64 %0, t; }" : "=r"(a) : "l"(p));
    return a;
}
__device__ __forceinline__ void ldsm4(uint32_t* r, uint32_t addr) {
    asm volatile("ldmatrix.sync.aligned.m8n8.x4.shared.b16 {%0,%1,%2,%3}, [%4];"
        : "=r"(r[0]), "=r"(r[1]), "=r"(r[2]), "=r"(r[3]) : "r"(addr));
}
__device__ __forceinline__ void mma16816(float* d, const uint32_t* a, const uint32_t* b) {
    asm volatile(
        "mma.sync.aligned.m16n8k16.row.col.f32.f16.f16.f32 "
        "{%0,%1,%2,%3}, {%4,%5,%6,%7}, {%8,%9}, {%0,%1,%2,%3};"
        : "+f"(d[0]), "+f"(d[1]), "+f"(d[2]), "+f"(d[3])
        : "r"(a[0]), "r"(a[1]), "r"(a[2]), "r"(a[3]), "r"(b[0]), "r"(b[1]));
}

// ------------------- weight prep ---------------------------------------------
__global__ void prep_w_kernel(const float* __restrict__ Wm, const float* __restrict__ W1,
                              const float* __restrict__ W2,
                              const float* __restrict__ attS2, const float* __restrict__ attD2)
{
    int i = blockIdx.x * 256 + threadIdx.x;
    if (i < 16384)      { int n = i >> 7, k = i & 127; g_B1[i] = __float2half(Wm[k * 128 + n]); }
    else if (i < 24576) { int j = i - 16384; int n = j >> 7, k = j & 127; g_B2[j] = __float2half(W1[k * 64 + n]); }
    else if (i < 32768) { int j = i - 24576; int n = j >> 6, k = j & 63;  g_B3[j] = __float2half(W2[k * 128 + n]); }
    else if (i < 32832) {
        int k = i - 32768;
        float s = 0.f, d = 0.f;
        const float* row = W2 + k * 128;
#pragma unroll 4
        for (int n = 0; n < 128; n++) {
            s = fmaf(row[n], attS2[n], s);
            d = fmaf(row[n], attD2[n], d);
        }
        g_wsd[k] = s;
        g_wsd[64 + k] = d;
    }
}

// ------------------- fused GEMM1+GEMM2 (+att1) --------------------------------
__global__ void __launch_bounds__(256, 2) gemm12_kernel(
    const float* __restrict__ A32,
    const float* __restrict__ bias,
    const float* __restrict__ attS, const float* __restrict__ attD,
    __half* __restrict__ outh1,
    float* __restrict__ asrc, float* __restrict__ adst,
    int M)
{
    constexpr int LDA = 136;
    const int tid = threadIdx.x;
    const int warp = tid >> 5;
    const int lane = tid & 31;
    const int gid = lane >> 2;
    const int tig = lane & 3;
    const int row0 = blockIdx.x * 128;
    const int WM = (warp & 3) * 32;
    const int WN1 = (warp >> 2) * 64;
    const int WN2 = (warp >> 2) * 32;

    extern __shared__ char sm[];
    __half* sA  = (__half*)sm;
    __half* sB1 = sA + 128 * LDA;
    __half* sB2 = sB1 + 128 * LDA;
    float* sBias = (float*)(sB2 + 64 * LDA);
    float* sAS = sBias + 128;
    float* sAD = sAS + 64;

    for (int idx = tid; idx < 128 * 32; idx += 256) {
        int r = idx >> 5;
        int c = (idx & 31) * 4;
        int gr = row0 + r;
        float4 v = make_float4(0.f, 0.f, 0.f, 0.f);
        if (gr < M) v = *(const float4*)(A32 + (size_t)gr * 128 + c);
        __half2 p0 = __floats2half2_rn(v.x, v.y);
        __half2 p1 = __floats2half2_rn(v.z, v.w);
        *(uint2*)(sA + r * LDA + c) = make_uint2(*(uint32_t*)&p0, *(uint32_t*)&p1);
    }
    for (int idx = tid; idx < 128 * 16; idx += 256) {
        int n = idx >> 4;
        int c = (idx & 15) * 8;
        *(uint4*)(sB1 + n * LDA + c) = *(const uint4*)(g_B1 + n * 128 + c);
    }
    for (int idx = tid; idx < 64 * 16; idx += 256) {
        int n = idx >> 4;
        int c = (idx & 15) * 8;
        *(uint4*)(sB2 + n * LDA + c) = *(const uint4*)(g_B2 + n * 128 + c);
    }
    if (tid < 128) sBias[tid] = bias[tid];
    if (tid < 64) { sAS[tid] = attS[tid]; sAD[tid] = attD[tid]; }
    __syncthreads();

    const uint32_t uA = smem_u32(sA), uB1 = smem_u32(sB1), uB2 = smem_u32(sB2);
    const int a0off = (WM + (lane & 15)) * LDA + (lane >> 4) * 8;
    const int a1off = a0off + 16 * LDA;
    const int brow = lane & 7;
    const int bhalf = (lane >> 3) & 1;
    const int bsel = (lane >> 4) * 8 + brow;

    float acc[2][8][4];
#pragma unroll
    for (int m = 0; m < 2; m++)
#pragma unroll
        for (int t = 0; t < 8; t++)
#pragma unroll
            for (int j = 0; j < 4; j++) acc[m][t][j] = 0.f;

#pragma unroll
    for (int ks = 0; ks < 8; ks++) {
        uint32_t a0[4], a1[4];
        ldsm4(a0, uA + (uint32_t)(a0off + ks * 16) * 2);
        ldsm4(a1, uA + (uint32_t)(a1off + ks * 16) * 2);
#pragma unroll
        for (int p = 0; p < 4; p++) {
            int boff = (WN1 + p * 16 + bsel) * LDA + ks * 16 + bhalf * 8;
            uint32_t b[4];
            ldsm4(b, uB1 + (uint32_t)boff * 2);
            mma16816(acc[0][2 * p],     a0, b);
            mma16816(acc[0][2 * p + 1], a0, b + 2);
            mma16816(acc[1][2 * p],     a1, b);
            mma16816(acc[1][2 * p + 1], a1, b + 2);
        }
    }
    __syncthreads();

#pragma unroll
    for (int m = 0; m < 2; m++) {
        int lr0 = WM + m * 16 + gid;
        int lr1 = lr0 + 8;
#pragma unroll
        for (int t = 0; t < 8; t++) {
            int c = WN1 + t * 8 + tig * 2;
            __half2 p0 = __floats2half2_rn(acc[m][t][0] + sBias[c], acc[m][t][1] + sBias[c + 1]);
            __half2 p1 = __floats2half2_rn(acc[m][t][2] + sBias[c], acc[m][t][3] + sBias[c + 1]);
            *(uint32_t*)(sA + lr0 * LDA + c) = *(uint32_t*)&p0;
            *(uint32_t*)(sA + lr1 * LDA + c) = *(uint32_t*)&p1;
        }
    }
    __syncthreads();

    float acc2[2][4][4];
#pragma unroll
    for (int m = 0; m < 2; m++)
#pragma unroll
        for (int t = 0; t < 4; t++)
#pragma unroll
            for (int j = 0; j < 4; j++) acc2[m][t][j] = 0.f;

#pragma unroll
    for (int ks = 0; ks < 8; ks++) {
        uint32_t a0[4], a1[4];
        ldsm4(a0, uA + (uint32_t)(a0off + ks * 16) * 2);
        ldsm4(a1, uA + (uint32_t)(a1off + ks * 16) * 2);
#pragma unroll
        for (int p = 0; p < 2; p++) {
            int boff = (WN2 + p * 16 + bsel) * LDA + ks * 16 + bhalf * 8;
            uint32_t b[4];
            ldsm4(b, uB2 + (uint32_t)boff * 2);
            mma16816(acc2[0][2 * p],     a0, b);
            mma16816(acc2[0][2 * p + 1], a0, b + 2);
            mma16816(acc2[1][2 * p],     a1, b);
            mma16816(acc2[1][2 * p + 1], a1, b + 2);
        }
    }

#pragma unroll
    for (int m = 0; m < 2; m++) {
        int r0 = row0 + WM + m * 16 + gid;
        int r1 = r0 + 8;
#pragma unroll
        for (int t = 0; t < 4; t++) {
            int c = WN2 + t * 8 + tig * 2;
            int head = (WN2 >> 3) + t;
            float sl  = acc2[m][t][0] * sAS[c] + acc2[m][t][1] * sAS[c + 1];
            float shh = acc2[m][t][2] * sAS[c] + acc2[m][t][3] * sAS[c + 1];
            float dl  = acc2[m][t][0] * sAD[c] + acc2[m][t][1] * sAD[c + 1];
            float dhh = acc2[m][t][2] * sAD[c] + acc2[m][t][3] * sAD[c + 1];
#pragma unroll
            for (int o = 1; o < 4; o <<= 1) {
                sl  += __shfl_xor_sync(FULLM, sl, o);
                shh += __shfl_xor_sync(FULLM, shh, o);
                dl  += __shfl_xor_sync(FULLM, dl, o);
                dhh += __shfl_xor_sync(FULLM, dhh, o);
            }
            if (tig == 0) {
                if (r0 < M) { asrc[(size_t)r0 * 8 + head] = sl;  adst[(size_t)r0 * 8 + head] = dl; }
                if (r1 < M) { asrc[(size_t)r1 * 8 + head] = shh; adst[(size_t)r1 * 8 + head] = dhh; }
            }
            __half2 p0 = __floats2half2_rn(acc2[m][t][0], acc2[m][t][1]);
            __half2 p1 = __floats2half2_rn(acc2[m][t][2], acc2[m][t][3]);
            if (r0 < M) *(uint32_t*)(outh1 + (size_t)r0 * 64 + c) = *(uint32_t*)&p0;
            if (r1 < M) *(uint32_t*)(outh1 + (size_t)r1 * 64 + c) = *(uint32_t*)&p1;
        }
    }
}
#define SMEM_G12 ((128 + 128 + 64) * 136 * 2 + 128 * 4 + 64 * 8 + 256)

// ------------------- GEMM3: out = aggh @ W2 + b2 ------------------------------
__global__ void __launch_bounds__(256) gemm3_kernel(
    const __half* __restrict__ Ag,
    const float* __restrict__ bias,
    float* __restrict__ out,
    int M)
{
    constexpr int K = 64, NC = 128, LDA = 72;
    const int tid = threadIdx.x;
    const int warp = tid >> 5;
    const int lane = tid & 31;
    const int gid = lane >> 2;
    const int tig = lane & 3;
    const int row0 = blockIdx.x * 128;
    const int WM = (warp & 3) * 32;
    const int WN = (warp >> 2) * 64;

    extern __shared__ char sm[];
    __half* sA = (__half*)sm;
    __half* sB = sA + 128 * LDA;
    float* sBias = (float*)(sB + NC * LDA);

    for (int idx = tid; idx < 128 * (K / 8); idx += 256) {
        int r = idx / (K / 8);
        int c = (idx % (K / 8)) * 8;
        int gr = row0 + r;
        uint4 v = make_uint4(0, 0, 0, 0);
        if (gr < M) v = *(const uint4*)(Ag + (size_t)gr * K + c);
        *(uint4*)(sA + r * LDA + c) = v;
    }
    for (int idx = tid; idx < NC * (K / 8); idx += 256) {
        int n = idx / (K / 8);
        int c = (idx % (K / 8)) * 8;
        *(uint4*)(sB + n * LDA + c) = *(const uint4*)(g_B3 + n * K + c);
    }
    if (tid < NC) sBias[tid] = bias[tid];
    __syncthreads();

    float acc[2][8][4];
#pragma unroll
    for (int m = 0; m < 2; m++)
#pragma unroll
        for (int t = 0; t < 8; t++)
#pragma unroll
            for (int j = 0; j < 4; j++) acc[m][t][j] = 0.f;

    const uint32_t uA = smem_u32(sA), uB = smem_u32(sB);
    const int a0off = (WM + (lane & 15)) * LDA + (lane >> 4) * 8;
    const int a1off = a0off + 16 * LDA;
    const int brow = lane & 7;
    const int bhalf = (lane >> 3) & 1;
    const int bsel = (lane >> 4) * 8 + brow;

#pragma unroll
    for (int ks = 0; ks < K / 16; ks++) {
        uint32_t a0[4], a1[4];
        ldsm4(a0, uA + (uint32_t)(a0off + ks * 16) * 2);
        ldsm4(a1, uA + (uint32_t)(a1off + ks * 16) * 2);
#pragma unroll
        for (int p = 0; p < 4; p++) {
            int boff = (WN + p * 16 + bsel) * LDA + ks * 16 + bhalf * 8;
            uint32_t b[4];
            ldsm4(b, uB + (uint32_t)boff * 2);
            mma16816(acc[0][2 * p],     a0, b);
            mma16816(acc[0][2 * p + 1], a0, b + 2);
            mma16816(acc[1][2 * p],     a1, b);
            mma16816(acc[1][2 * p + 1], a1, b + 2);
        }
    }

#pragma unroll
    for (int m = 0; m < 2; m++) {
        int r0 = row0 + WM + m * 16 + gid;
        int r1 = r0 + 8;
#pragma unroll
        for (int t = 0; t < 8; t++) {
            int c = WN + t * 8 + tig * 2;
            float b0 = sBias[c], b1v = sBias[c + 1];
            if (r0 < M) {
                float2 v = make_float2(acc[m][t][0] + b0, acc[m][t][1] + b1v);
                *(float2*)(out + (size_t)r0 * NC + c) = v;
            }
            if (r1 < M) {
                float2 v = make_float2(acc[m][t][2] + b0, acc[m][t][3] + b1v);
                *(float2*)(out + (size_t)r1 * NC + c) = v;
            }
        }
    }
}
#define SMEM_G3 ((128 + 128) * 72 * 2 + 128 * 4 + 256)

// ------------------- static init ---------------------------------------------
struct HxInit {
    cudaStream_t s2;
    cudaEvent_t evF, evJ;
    HxInit() {
        cudaStreamCreateWithFlags(&s2, cudaStreamNonBlocking);
        cudaEventCreateWithFlags(&evF, cudaEventDisableTiming);
        cudaEventCreateWithFlags(&evJ, cudaEventDisableTiming);
        cudaFuncSetAttribute(gemm12_kernel, cudaFuncAttributeMaxDynamicSharedMemorySize, SMEM_G12);
        cudaFuncSetAttribute(gemm3_kernel,  cudaFuncAttributeMaxDynamicSharedMemorySize, SMEM_G3);
    }
};
static HxInit g_hx;

// ------------------- CSR build (proven 3-kernel scan + rank scatter) ---------
__global__ void init_kernel()
{
    int i = blockIdx.x * 256 + threadIdx.x;
    if (i < NN) g_counts[i] = 1;   // slot 0 reserved for self loop
}

__global__ void count_kernel(const int* __restrict__ dst)
{
    int e = blockIdx.x * 256 + threadIdx.x;
    if (e < EE) g_erank[e] = atomicAdd(&g_counts[dst[e]], 1);
}

__global__ void __launch_bounds__(1024) scan1_kernel()
{
    __shared__ int wsum[32];
    int tid = threadIdx.x, lane = tid & 31, wid = tid >> 5;
    int idx = blockIdx.x * 1024 + tid;
    int v = (idx < NN) ? g_counts[idx] : 0;
    int x = v;
#pragma unroll
    for (int off = 1; off < 32; off <<= 1) {
        int y = __shfl_up_sync(FULLM, x, off);
        if (lane >= off) x += y;
    }
    if (lane == 31) wsum[wid] = x;
    __syncthreads();
    if (wid == 0) {
        int wv = wsum[lane];
#pragma unroll
        for (int off = 1; off < 32; off <<= 1) {
            int y = __shfl_up_sync(FULLM, wv, off);
            if (lane >= off) wv += y;
        }
        wsum[lane] = wv;
    }
    __syncthreads();
    int pre = (wid > 0) ? wsum[wid - 1] : 0;
    if (idx < NN) g_rowoff[idx] = x + pre - v;
    if (tid == 1023) g_blocksum[blockIdx.x] = x + pre;
}

__global__ void __launch_bounds__(64) scan2_kernel(int nblocks)
{
    __shared__ int s0tot;
    int tid = threadIdx.x, lane = tid & 31, wid = tid >> 5;
    int v = (tid < nblocks) ? g_blocksum[tid] : 0;
    int x = v;
#pragma unroll
    for (int off = 1; off < 32; off <<= 1) {
        int y = __shfl_up_sync(FULLM, x, off);
        if (lane >= off) x += y;
    }
    if (wid == 0 && lane == 31) s0tot = x;
    __syncthreads();
    int pre = (wid == 1) ? s0tot : 0;
    int excl = x - v + pre;
    if (tid < nblocks) g_blocksum[tid] = excl;
    if (tid == nblocks - 1) g_rowoff[NN] = excl + v;
}

__global__ void __launch_bounds__(1024) scan3_kernel()
{
    int idx = blockIdx.x * 1024 + threadIdx.x;
    if (idx < NN) {
        int off = g_rowoff[idx] + g_blocksum[blockIdx.x];
        g_rowoff[idx] = off;
        g_csrsrc[off] = idx;    // self loop
    }
}

__global__ void scatter_kernel(const int* __restrict__ src, const int* __restrict__ dst)
{
    int e = blockIdx.x * 256 + threadIdx.x;
    if (e < EE) {
        int d = dst[e];
        g_csrsrc[g_rowoff[d] + g_erank[e]] = src[e];
    }
}

// ------------------- GAT conv1 aggregation (lane-parallel weights) -----------
__global__ void __launch_bounds__(256) agg1_kernel(const float* __restrict__ b1)
{
    int w = (blockIdx.x * blockDim.x + threadIdx.x) >> 5;
    int lane = threadIdx.x & 31;
    if (w >= NN) return;
    int head = lane >> 2;
    int c0 = lane * 2;
    int beg = g_rowoff[w], end = g_rowoff[w + 1];

    float ad8 = g_adst1[w * 8 + (lane & 7)];
    float adh = __shfl_sync(FULLM, ad8, head);

    float a0 = 0.f, a1 = 0.f, sSum = 0.f;
    float b0a = 0.f, b1a = 0.f;
    float c0a = 0.f, c1a = 0.f;
    float d0a = 0.f, d1a = 0.f;

    for (int base = beg; base < end; base += 32) {
        int n = end - base;
        int kmax = n < 32 ? n : 32;
        int sl = (lane < kmax) ? g_csrsrc[base + lane] : 0;
        int k = 0;
        for (; k + 4 <= kmax; k += 4) {
            int sj = __shfl_sync(FULLM, sl, k + (lane >> 3));
            float e4 = __expf(leaky(g_asrc1[sj * 8 + (lane & 7)] + ad8));
            int s0 = __shfl_sync(FULLM, sl, k);
            int s1 = __shfl_sync(FULLM, sl, k + 1);
            int s2 = __shfl_sync(FULLM, sl, k + 2);
            int s3 = __shfl_sync(FULLM, sl, k + 3);
            float e0 = __shfl_sync(FULLM, e4, head);
            float e1 = __shfl_sync(FULLM, e4, 8 + head);
            float e2 = __shfl_sync(FULLM, e4, 16 + head);
            float e3 = __shfl_sync(FULLM, e4, 24 + head);
            float2 h0 = __half22float2(*(const __half2*)(g_h1h + s0 * 64 + c0));
            float2 h1 = __half22float2(*(const __half2*)(g_h1h + s1 * 64 + c0));
            float2 h2 = __half22float2(*(const __half2*)(g_h1h + s2 * 64 + c0));
            float2 h3 = __half22float2(*(const __half2*)(g_h1h + s3 * 64 + c0));
            a0 = fmaf(e0, h0.x, a0);  a1 = fmaf(e0, h0.y, a1);
            b0a = fmaf(e1, h1.x, b0a); b1a = fmaf(e1, h1.y, b1a);
            c0a = fmaf(e2, h2.x, c0a); c1a = fmaf(e2, h2.y, c1a);
            d0a = fmaf(e3, h3.x, d0a); d1a = fmaf(e3, h3.y, d1a);
            sSum += e0 + e1 + e2 + e3;
        }
        for (; k < kmax; k++) {
            int s = __shfl_sync(FULLM, sl, k);
            float e = __expf(leaky(g_asrc1[s * 8 + head] + adh));
            float2 hv = __half22float2(*(const __half2*)(g_h1h + s * 64 + c0));
            a0 = fmaf(e, hv.x, a0); a1 = fmaf(e, hv.y, a1);
            sSum += e;
        }
    }
    a0 += b0a + c0a + d0a;
    a1 += b1a + c1a + d1a;
    float inv = 1.f / sSum;
    float o0 = a0 * inv + b1[c0];
    float o1 = a1 * inv + b1[c0 + 1];
    o0 = o0 > 0.f ? o0 : expm1f(o0);
    o1 = o1 > 0.f ? o1 : expm1f(o1);
    __half2 p = __floats2half2_rn(o0, o1);
    *(uint32_t*)(g_hm + w * 64 + c0) = *(uint32_t*)&p;

    float ps = o0 * g_wsd[c0] + o1 * g_wsd[c0 + 1];
    float pd = o0 * g_wsd[64 + c0] + o1 * g_wsd[64 + c0 + 1];
#pragma unroll
    for (int off = 16; off; off >>= 1) {
        ps += __shfl_xor_sync(FULLM, ps, off);
        pd += __shfl_xor_sync(FULLM, pd, off);
    }
    if (lane == 0) { g_asrc2[w] = ps; g_adst2[w] = pd; }
}

// ------------------- GAT conv2 aggregation (4-wide staged consume) -----------
__global__ void __launch_bounds__(256) agg2_kernel()
{
    int w = (blockIdx.x * blockDim.x + threadIdx.x) >> 5;
    int lane = threadIdx.x & 31;
    if (w >= NN) return;
    int c0 = lane * 2;
    int beg = g_rowoff[w], end = g_rowoff[w + 1];
    float adh = g_adst2[w];

    float a0 = 0.f, a1 = 0.f, sSum = 0.f;
    float b0a = 0.f, b1a = 0.f;
    float c0a = 0.f, c1a = 0.f;
    float d0a = 0.f, d1a = 0.f;

    for (int base = beg; base < end; base += 32) {
        int n = end - base;
        int kmax = n < 32 ? n : 32;
        int sl = 0;
        float el = 0.f;
        if (lane < kmax) {
            sl = g_csrsrc[base + lane];
            el = __expf(leaky(g_asrc2[sl] + adh));
        }
        sSum += el;
        int k = 0;
        for (; k + 4 <= kmax; k += 4) {
            int s0 = __shfl_sync(FULLM, sl, k);
            int s1 = __shfl_sync(FULLM, sl, k + 1);
            int s2 = __shfl_sync(FULLM, sl, k + 2);
            int s3 = __shfl_sync(FULLM, sl, k + 3);
            float e0 = __shfl_sync(FULLM, el, k);
            float e1 = __shfl_sync(FULLM, el, k + 1);
            float e2 = __shfl_sync(FULLM, el, k + 2);
            float e3 = __shfl_sync(FULLM, el, k + 3);
            float2 h0 = __half22float2(*(const __half2*)(g_hm + s0 * 64 + c0));
            float2 h1 = __half22float2(*(const __half2*)(g_hm + s1 * 64 + c0));
            float2 h2 = __half22float2(*(const __half2*)(g_hm + s2 * 64 + c0));
            float2 h3 = __half22float2(*(const __half2*)(g_hm + s3 * 64 + c0));
            a0 = fmaf(e0, h0.x, a0);  a1 = fmaf(e0, h0.y, a1);
            b0a = fmaf(e1, h1.x, b0a); b1a = fmaf(e1, h1.y, b1a);
            c0a = fmaf(e2, h2.x, c0a); c1a = fmaf(e2, h2.y, c1a);
            d0a = fmaf(e3, h3.x, d0a); d1a = fmaf(e3, h3.y, d1a);
        }
        for (; k < kmax; k++) {
            int s = __shfl_sync(FULLM, sl, k);
            float e = __shfl_sync(FULLM, el, k);
            float2 hv = __half22float2(*(const __half2*)(g_hm + s * 64 + c0));
            a0 = fmaf(e, hv.x, a0); a1 = fmaf(e, hv.y, a1);
        }
    }
    a0 += b0a + c0a + d0a;
    a1 += b1a + c1a + d1a;
#pragma unroll
    for (int off = 16; off; off >>= 1)
        sSum += __shfl_xor_sync(FULLM, sSum, off);
    float inv = 1.f / sSum;
    __half2 p = __floats2half2_rn(a0 * inv, a1 * inv);
    *(uint32_t*)(g_aggh + w * 64 + c0) = *(uint32_t*)&p;
}

// ------------------- launch --------------------------------------------------
extern "C" void kernel_launch(void* const* d_in, const int* in_sizes, int n_in,
                              void* d_out, int out_size)
{
    (void)in_sizes; (void)n_in; (void)out_size;
    const float* x        = (const float*)d_in[0];
    const int*   ei       = (const int*)d_in[1];
    const float* W_map    = (const float*)d_in[2];
    const float* b_map    = (const float*)d_in[3];
    const float* W1       = (const float*)d_in[4];
    const float* att_src1 = (const float*)d_in[5];
    const float* att_dst1 = (const float*)d_in[6];
    const float* b1       = (const float*)d_in[7];
    const float* W2       = (const float*)d_in[8];
    const float* att_src2 = (const float*)d_in[9];
    const float* att_dst2 = (const float*)d_in[10];
    const float* b2       = (const float*)d_in[11];
    float* out = (float*)d_out;
    const int* src = ei;
    const int* dst = ei + EE;

    __half *p_h1h, *p_aggh;
    float *p_as1, *p_ad1;
    cudaGetSymbolAddress((void**)&p_h1h, g_h1h);
    cudaGetSymbolAddress((void**)&p_aggh, g_aggh);
    cudaGetSymbolAddress((void**)&p_as1, g_asrc1);
    cudaGetSymbolAddress((void**)&p_ad1, g_adst1);

    const int GEMM_BLOCKS = (NN + 127) / 128;
    const int N_BLOCKS    = (NN + 255) / 256;
    const int E_BLOCKS    = (EE + 255) / 256;
    const int WARP_BLOCKS = NN / 8;
    const int SCAN_BLOCKS = (NN + 1023) / 1024;

    cudaStream_t s2 = g_hx.s2;

    // fork FIRST: CSR arm starts at t=0; prep_w only gates the gemm arm
    cudaEventRecord(g_hx.evF, 0);
    cudaStreamWaitEvent(s2, g_hx.evF, 0);
    init_kernel<<<N_BLOCKS, 256, 0, s2>>>();
    count_kernel<<<E_BLOCKS, 256, 0, s2>>>(dst);

    prep_w_kernel<<<129, 256>>>(W_map, W1, W2, att_src2, att_dst2);
    gemm12_kernel<<<GEMM_BLOCKS, 256, SMEM_G12>>>(
        x, b_map, att_src1, att_dst1, p_h1h, p_as1, p_ad1, NN);

    scan1_kernel<<<SCAN_BLOCKS, 1024, 0, s2>>>();
    scan2_kernel<<<1, 64, 0, s2>>>(SCAN_BLOCKS);
    scan3_kernel<<<SCAN_BLOCKS, 1024, 0, s2>>>();
    scatter_kernel<<<E_BLOCKS, 256, 0, s2>>>(src, dst);
    cudaEventRecord(g_hx.evJ, s2);

    cudaStreamWaitEvent(0, g_hx.evJ, 0);

    agg1_kernel<<<WARP_BLOCKS, 256>>>(b1);
    agg2_kernel<<<WARP_BLOCKS, 256>>>();
    gemm3_kernel<<<GEMM_BLOCKS, 256, SMEM_G3>>>(p_aggh, b2, out, NN);
}

// round 17
// speedup vs baseline: 1.0752x; 1.0517x over previous
#include <cuda_runtime.h>
#include <cuda_fp16.h>
#include <math.h>
#include <stdint.h>

#define NN 50000
#define EE 1600000
#define ET (EE + NN)
#define FULLM 0xFFFFFFFFu

// ------------------- scratch (device globals; no allocation allowed) -------
__device__ __half g_h1h[NN * 64];
__device__ __half g_hm[NN * 64];
__device__ __half g_aggh[NN * 64];
__device__ float g_asrc1[NN * 8];
__device__ float g_adst1[NN * 8];
__device__ float g_asrc2[NN];
__device__ float g_adst2[NN];
__device__ int   g_counts[NN];
__device__ int   g_rowoff[NN + 1];
__device__ int   g_csrsrc[ET];
__device__ int   g_erank[EE];
__device__ int   g_blocksum[64];
__device__ float g_wsd[128];
// pre-transposed fp16 weights: Bt[n][k] = W[k][n]
__device__ __half g_B1[128 * 128];
__device__ __half g_B2[64 * 128];
__device__ __half g_B3[128 * 64];

__device__ __forceinline__ float leaky(float x) { return x > 0.f ? x : 0.2f * x; }

__device__ __forceinline__ uint32_t smem_u32(const void* p) {
    uint32_t a;
    asm("{ .reg .u64 t; cvta.to.shared.u64 t, %1; cvt.u32.u64 %0, t; }" : "=r"(a) : "l"(p));
    return a;
}
__device__ __forceinline__ void ldsm4(uint32_t* r, uint32_t addr) {
    asm volatile("ldmatrix.sync.aligned.m8n8.x4.shared.b16 {%0,%1,%2,%3}, [%4];"
        : "=r"(r[0]), "=r"(r[1]), "=r"(r[2]), "=r"(r[3]) : "r"(addr));
}
__device__ __forceinline__ void mma16816(float* d, const uint32_t* a, const uint32_t* b) {
    asm volatile(
        "mma.sync.aligned.m16n8k16.row.col.f32.f16.f16.f32 "
        "{%0,%1,%2,%3}, {%4,%5,%6,%7}, {%8,%9}, {%0,%1,%2,%3};"
        : "+f"(d[0]), "+f"(d[1]), "+f"(d[2]), "+f"(d[3])
        : "r"(a[0]), "r"(a[1]), "r"(a[2]), "r"(a[3]), "r"(b[0]), "r"(b[1]));
}

// ------------------- weight prep ---------------------------------------------
__global__ void prep_w_kernel(const float* __restrict__ Wm, const float* __restrict__ W1,
                              const float* __restrict__ W2,
                              const float* __restrict__ attS2, const float* __restrict__ attD2)
{
    int i = blockIdx.x * 256 + threadIdx.x;
    if (i < 16384)      { int n = i >> 7, k = i & 127; g_B1[i] = __float2half(Wm[k * 128 + n]); }
    else if (i < 24576) { int j = i - 16384; int n = j >> 7, k = j & 127; g_B2[j] = __float2half(W1[k * 64 + n]); }
    else if (i < 32768) { int j = i - 24576; int n = j >> 6, k = j & 63;  g_B3[j] = __float2half(W2[k * 128 + n]); }
    else if (i < 32832) {
        int k = i - 32768;
        float s = 0.f, d = 0.f;
        const float* row = W2 + k * 128;
#pragma unroll 4
        for (int n = 0; n < 128; n++) {
            s = fmaf(row[n], attS2[n], s);
            d = fmaf(row[n], attD2[n], d);
        }
        g_wsd[k] = s;
        g_wsd[64 + k] = d;
    }
}

// ------------------- fused GEMM1+GEMM2 (+att1) --------------------------------
__global__ void __launch_bounds__(256, 2) gemm12_kernel(
    const float* __restrict__ A32,
    const float* __restrict__ bias,
    const float* __restrict__ attS, const float* __restrict__ attD,
    __half* __restrict__ outh1,
    float* __restrict__ asrc, float* __restrict__ adst,
    int M)
{
    constexpr int LDA = 136;
    const int tid = threadIdx.x;
    const int warp = tid >> 5;
    const int lane = tid & 31;
    const int gid = lane >> 2;
    const int tig = lane & 3;
    const int row0 = blockIdx.x * 128;
    const int WM = (warp & 3) * 32;
    const int WN1 = (warp >> 2) * 64;
    const int WN2 = (warp >> 2) * 32;

    extern __shared__ char sm[];
    __half* sA  = (__half*)sm;
    __half* sB1 = sA + 128 * LDA;
    __half* sB2 = sB1 + 128 * LDA;
    float* sBias = (float*)(sB2 + 64 * LDA);
    float* sAS = sBias + 128;
    float* sAD = sAS + 64;

    for (int idx = tid; idx < 128 * 32; idx += 256) {
        int r = idx >> 5;
        int c = (idx & 31) * 4;
        int gr = row0 + r;
        float4 v = make_float4(0.f, 0.f, 0.f, 0.f);
        if (gr < M) v = *(const float4*)(A32 + (size_t)gr * 128 + c);
        __half2 p0 = __floats2half2_rn(v.x, v.y);
        __half2 p1 = __floats2half2_rn(v.z, v.w);
        *(uint2*)(sA + r * LDA + c) = make_uint2(*(uint32_t*)&p0, *(uint32_t*)&p1);
    }
    for (int idx = tid; idx < 128 * 16; idx += 256) {
        int n = idx >> 4;
        int c = (idx & 15) * 8;
        *(uint4*)(sB1 + n * LDA + c) = *(const uint4*)(g_B1 + n * 128 + c);
    }
    for (int idx = tid; idx < 64 * 16; idx += 256) {
        int n = idx >> 4;
        int c = (idx & 15) * 8;
        *(uint4*)(sB2 + n * LDA + c) = *(const uint4*)(g_B2 + n * 128 + c);
    }
    if (tid < 128) sBias[tid] = bias[tid];
    if (tid < 64) { sAS[tid] = attS[tid]; sAD[tid] = attD[tid]; }
    __syncthreads();

    const uint32_t uA = smem_u32(sA), uB1 = smem_u32(sB1), uB2 = smem_u32(sB2);
    const int a0off = (WM + (lane & 15)) * LDA + (lane >> 4) * 8;
    const int a1off = a0off + 16 * LDA;
    const int brow = lane & 7;
    const int bhalf = (lane >> 3) & 1;
    const int bsel = (lane >> 4) * 8 + brow;

    float acc[2][8][4];
#pragma unroll
    for (int m = 0; m < 2; m++)
#pragma unroll
        for (int t = 0; t < 8; t++)
#pragma unroll
            for (int j = 0; j < 4; j++) acc[m][t][j] = 0.f;

#pragma unroll
    for (int ks = 0; ks < 8; ks++) {
        uint32_t a0[4], a1[4];
        ldsm4(a0, uA + (uint32_t)(a0off + ks * 16) * 2);
        ldsm4(a1, uA + (uint32_t)(a1off + ks * 16) * 2);
#pragma unroll
        for (int p = 0; p < 4; p++) {
            int boff = (WN1 + p * 16 + bsel) * LDA + ks * 16 + bhalf * 8;
            uint32_t b[4];
            ldsm4(b, uB1 + (uint32_t)boff * 2);
            mma16816(acc[0][2 * p],     a0, b);
            mma16816(acc[0][2 * p + 1], a0, b + 2);
            mma16816(acc[1][2 * p],     a1, b);
            mma16816(acc[1][2 * p + 1], a1, b + 2);
        }
    }
    __syncthreads();

#pragma unroll
    for (int m = 0; m < 2; m++) {
        int lr0 = WM + m * 16 + gid;
        int lr1 = lr0 + 8;
#pragma unroll
        for (int t = 0; t < 8; t++) {
            int c = WN1 + t * 8 + tig * 2;
            __half2 p0 = __floats2half2_rn(acc[m][t][0] + sBias[c], acc[m][t][1] + sBias[c + 1]);
            __half2 p1 = __floats2half2_rn(acc[m][t][2] + sBias[c], acc[m][t][3] + sBias[c + 1]);
            *(uint32_t*)(sA + lr0 * LDA + c) = *(uint32_t*)&p0;
            *(uint32_t*)(sA + lr1 * LDA + c) = *(uint32_t*)&p1;
        }
    }
    __syncthreads();

    float acc2[2][4][4];
#pragma unroll
    for (int m = 0; m < 2; m++)
#pragma unroll
        for (int t = 0; t < 4; t++)
#pragma unroll
            for (int j = 0; j < 4; j++) acc2[m][t][j] = 0.f;

#pragma unroll
    for (int ks = 0; ks < 8; ks++) {
        uint32_t a0[4], a1[4];
        ldsm4(a0, uA + (uint32_t)(a0off + ks * 16) * 2);
        ldsm4(a1, uA + (uint32_t)(a1off + ks * 16) * 2);
#pragma unroll
        for (int p = 0; p < 2; p++) {
            int boff = (WN2 + p * 16 + bsel) * LDA + ks * 16 + bhalf * 8;
            uint32_t b[4];
            ldsm4(b, uB2 + (uint32_t)boff * 2);
            mma16816(acc2[0][2 * p],     a0, b);
            mma16816(acc2[0][2 * p + 1], a0, b + 2);
            mma16816(acc2[1][2 * p],     a1, b);
            mma16816(acc2[1][2 * p + 1], a1, b + 2);
        }
    }

#pragma unroll
    for (int m = 0; m < 2; m++) {
        int r0 = row0 + WM + m * 16 + gid;
        int r1 = r0 + 8;
#pragma unroll
        for (int t = 0; t < 4; t++) {
            int c = WN2 + t * 8 + tig * 2;
            int head = (WN2 >> 3) + t;
            float sl  = acc2[m][t][0] * sAS[c] + acc2[m][t][1] * sAS[c + 1];
            float shh = acc2[m][t][2] * sAS[c] + acc2[m][t][3] * sAS[c + 1];
            float dl  = acc2[m][t][0] * sAD[c] + acc2[m][t][1] * sAD[c + 1];
            float dhh = acc2[m][t][2] * sAD[c] + acc2[m][t][3] * sAD[c + 1];
#pragma unroll
            for (int o = 1; o < 4; o <<= 1) {
                sl  += __shfl_xor_sync(FULLM, sl, o);
                shh += __shfl_xor_sync(FULLM, shh, o);
                dl  += __shfl_xor_sync(FULLM, dl, o);
                dhh += __shfl_xor_sync(FULLM, dhh, o);
            }
            if (tig == 0) {
                if (r0 < M) { asrc[(size_t)r0 * 8 + head] = sl;  adst[(size_t)r0 * 8 + head] = dl; }
                if (r1 < M) { asrc[(size_t)r1 * 8 + head] = shh; adst[(size_t)r1 * 8 + head] = dhh; }
            }
            __half2 p0 = __floats2half2_rn(acc2[m][t][0], acc2[m][t][1]);
            __half2 p1 = __floats2half2_rn(acc2[m][t][2], acc2[m][t][3]);
            if (r0 < M) *(uint32_t*)(outh1 + (size_t)r0 * 64 + c) = *(uint32_t*)&p0;
            if (r1 < M) *(uint32_t*)(outh1 + (size_t)r1 * 64 + c) = *(uint32_t*)&p1;
        }
    }
}
#define SMEM_G12 ((128 + 128 + 64) * 136 * 2 + 128 * 4 + 64 * 8 + 256)

// ------------------- GEMM3: out = aggh @ W2 + b2 ------------------------------
__global__ void __launch_bounds__(256) gemm3_kernel(
    const __half* __restrict__ Ag,
    const float* __restrict__ bias,
    float* __restrict__ out,
    int M)
{
    constexpr int K = 64, NC = 128, LDA = 72;
    const int tid = threadIdx.x;
    const int warp = tid >> 5;
    const int lane = tid & 31;
    const int gid = lane >> 2;
    const int tig = lane & 3;
    const int row0 = blockIdx.x * 128;
    const int WM = (warp & 3) * 32;
    const int WN = (warp >> 2) * 64;

    extern __shared__ char sm[];
    __half* sA = (__half*)sm;
    __half* sB = sA + 128 * LDA;
    float* sBias = (float*)(sB + NC * LDA);

    for (int idx = tid; idx < 128 * (K / 8); idx += 256) {
        int r = idx / (K / 8);
        int c = (idx % (K / 8)) * 8;
        int gr = row0 + r;
        uint4 v = make_uint4(0, 0, 0, 0);
        if (gr < M) v = *(const uint4*)(Ag + (size_t)gr * K + c);
        *(uint4*)(sA + r * LDA + c) = v;
    }
    for (int idx = tid; idx < NC * (K / 8); idx += 256) {
        int n = idx / (K / 8);
        int c = (idx % (K / 8)) * 8;
        *(uint4*)(sB + n * LDA + c) = *(const uint4*)(g_B3 + n * K + c);
    }
    if (tid < NC) sBias[tid] = bias[tid];
    __syncthreads();

    float acc[2][8][4];
#pragma unroll
    for (int m = 0; m < 2; m++)
#pragma unroll
        for (int t = 0; t < 8; t++)
#pragma unroll
            for (int j = 0; j < 4; j++) acc[m][t][j] = 0.f;

    const uint32_t uA = smem_u32(sA), uB = smem_u32(sB);
    const int a0off = (WM + (lane & 15)) * LDA + (lane >> 4) * 8;
    const int a1off = a0off + 16 * LDA;
    const int brow = lane & 7;
    const int bhalf = (lane >> 3) & 1;
    const int bsel = (lane >> 4) * 8 + brow;

#pragma unroll
    for (int ks = 0; ks < K / 16; ks++) {
        uint32_t a0[4], a1[4];
        ldsm4(a0, uA + (uint32_t)(a0off + ks * 16) * 2);
        ldsm4(a1, uA + (uint32_t)(a1off + ks * 16) * 2);
#pragma unroll
        for (int p = 0; p < 4; p++) {
            int boff = (WN + p * 16 + bsel) * LDA + ks * 16 + bhalf * 8;
            uint32_t b[4];
            ldsm4(b, uB + (uint32_t)boff * 2);
            mma16816(acc[0][2 * p],     a0, b);
            mma16816(acc[0][2 * p + 1], a0, b + 2);
            mma16816(acc[1][2 * p],     a1, b);
            mma16816(acc[1][2 * p + 1], a1, b + 2);
        }
    }

#pragma unroll
    for (int m = 0; m < 2; m++) {
        int r0 = row0 + WM + m * 16 + gid;
        int r1 = r0 + 8;
#pragma unroll
        for (int t = 0; t < 8; t++) {
            int c = WN + t * 8 + tig * 2;
            float b0 = sBias[c], b1v = sBias[c + 1];
            if (r0 < M) {
                float2 v = make_float2(acc[m][t][0] + b0, acc[m][t][1] + b1v);
                *(float2*)(out + (size_t)r0 * NC + c) = v;
            }
            if (r1 < M) {
                float2 v = make_float2(acc[m][t][2] + b0, acc[m][t][3] + b1v);
                *(float2*)(out + (size_t)r1 * NC + c) = v;
            }
        }
    }
}
#define SMEM_G3 ((128 + 128) * 72 * 2 + 128 * 4 + 256)

// ------------------- static init ---------------------------------------------
struct HxInit {
    cudaStream_t s2;
    cudaEvent_t evF, evJ;
    HxInit() {
        cudaStreamCreateWithFlags(&s2, cudaStreamNonBlocking);
        cudaEventCreateWithFlags(&evF, cudaEventDisableTiming);
        cudaEventCreateWithFlags(&evJ, cudaEventDisableTiming);
        cudaFuncSetAttribute(gemm12_kernel, cudaFuncAttributeMaxDynamicSharedMemorySize, SMEM_G12);
        cudaFuncSetAttribute(gemm3_kernel,  cudaFuncAttributeMaxDynamicSharedMemorySize, SMEM_G3);
    }
};
static HxInit g_hx;

// ------------------- CSR build (proven 3-kernel scan + rank scatter) ---------
__global__ void init_kernel()
{
    int i = blockIdx.x * 256 + threadIdx.x;
    if (i < NN) g_counts[i] = 1;   // slot 0 reserved for self loop
}

__global__ void count_kernel(const int* __restrict__ dst)
{
    int e = blockIdx.x * 256 + threadIdx.x;
    if (e < EE) g_erank[e] = atomicAdd(&g_counts[dst[e]], 1);
}

__global__ void __launch_bounds__(1024) scan1_kernel()
{
    __shared__ int wsum[32];
    int tid = threadIdx.x, lane = tid & 31, wid = tid >> 5;
    int idx = blockIdx.x * 1024 + tid;
    int v = (idx < NN) ? g_counts[idx] : 0;
    int x = v;
#pragma unroll
    for (int off = 1; off < 32; off <<= 1) {
        int y = __shfl_up_sync(FULLM, x, off);
        if (lane >= off) x += y;
    }
    if (lane == 31) wsum[wid] = x;
    __syncthreads();
    if (wid == 0) {
        int wv = wsum[lane];
#pragma unroll
        for (int off = 1; off < 32; off <<= 1) {
            int y = __shfl_up_sync(FULLM, wv, off);
            if (lane >= off) wv += y;
        }
        wsum[lane] = wv;
    }
    __syncthreads();
    int pre = (wid > 0) ? wsum[wid - 1] : 0;
    if (idx < NN) g_rowoff[idx] = x + pre - v;
    if (tid == 1023) g_blocksum[blockIdx.x] = x + pre;
}

__global__ void __launch_bounds__(64) scan2_kernel(int nblocks)
{
    __shared__ int s0tot;
    int tid = threadIdx.x, lane = tid & 31, wid = tid >> 5;
    int v = (tid < nblocks) ? g_blocksum[tid] : 0;
    int x = v;
#pragma unroll
    for (int off = 1; off < 32; off <<= 1) {
        int y = __shfl_up_sync(FULLM, x, off);
        if (lane >= off) x += y;
    }
    if (wid == 0 && lane == 31) s0tot = x;
    __syncthreads();
    int pre = (wid == 1) ? s0tot : 0;
    int excl = x - v + pre;
    if (tid < nblocks) g_blocksum[tid] = excl;
    if (tid == nblocks - 1) g_rowoff[NN] = excl + v;
}

__global__ void __launch_bounds__(1024) scan3_kernel()
{
    int idx = blockIdx.x * 1024 + threadIdx.x;
    if (idx < NN) {
        int off = g_rowoff[idx] + g_blocksum[blockIdx.x];
        g_rowoff[idx] = off;
        g_csrsrc[off] = idx;    // self loop
    }
}

__global__ void scatter_kernel(const int* __restrict__ src, const int* __restrict__ dst)
{
    int e = blockIdx.x * 256 + threadIdx.x;
    if (e < EE) {
        int d = dst[e];
        g_csrsrc[g_rowoff[d] + g_erank[e]] = src[e];
    }
}

// ------------------- GAT conv1 aggregation (lane-parallel weights) -----------
__global__ void __launch_bounds__(256) agg1_kernel(const float* __restrict__ b1)
{
    int w = (blockIdx.x * blockDim.x + threadIdx.x) >> 5;
    int lane = threadIdx.x & 31;
    if (w >= NN) return;
    int head = lane >> 2;
    int c0 = lane * 2;
    int beg = g_rowoff[w], end = g_rowoff[w + 1];

    float ad8 = g_adst1[w * 8 + (lane & 7)];
    float adh = __shfl_sync(FULLM, ad8, head);

    float a0 = 0.f, a1 = 0.f, sSum = 0.f;
    float b0a = 0.f, b1a = 0.f;
    float c0a = 0.f, c1a = 0.f;
    float d0a = 0.f, d1a = 0.f;

    for (int base = beg; base < end; base += 32) {
        int n = end - base;
        int kmax = n < 32 ? n : 32;
        int sl = (lane < kmax) ? g_csrsrc[base + lane] : 0;
        int k = 0;
        for (; k + 4 <= kmax; k += 4) {
            int sj = __shfl_sync(FULLM, sl, k + (lane >> 3));
            float e4 = __expf(leaky(g_asrc1[sj * 8 + (lane & 7)] + ad8));
            int s0 = __shfl_sync(FULLM, sl, k);
            int s1 = __shfl_sync(FULLM, sl, k + 1);
            int s2 = __shfl_sync(FULLM, sl, k + 2);
            int s3 = __shfl_sync(FULLM, sl, k + 3);
            float e0 = __shfl_sync(FULLM, e4, head);
            float e1 = __shfl_sync(FULLM, e4, 8 + head);
            float e2 = __shfl_sync(FULLM, e4, 16 + head);
            float e3 = __shfl_sync(FULLM, e4, 24 + head);
            float2 h0 = __half22float2(*(const __half2*)(g_h1h + s0 * 64 + c0));
            float2 h1 = __half22float2(*(const __half2*)(g_h1h + s1 * 64 + c0));
            float2 h2 = __half22float2(*(const __half2*)(g_h1h + s2 * 64 + c0));
            float2 h3 = __half22float2(*(const __half2*)(g_h1h + s3 * 64 + c0));
            a0 = fmaf(e0, h0.x, a0);  a1 = fmaf(e0, h0.y, a1);
            b0a = fmaf(e1, h1.x, b0a); b1a = fmaf(e1, h1.y, b1a);
            c0a = fmaf(e2, h2.x, c0a); c1a = fmaf(e2, h2.y, c1a);
            d0a = fmaf(e3, h3.x, d0a); d1a = fmaf(e3, h3.y, d1a);
            sSum += e0 + e1 + e2 + e3;
        }
        for (; k < kmax; k++) {
            int s = __shfl_sync(FULLM, sl, k);
            float e = __expf(leaky(g_asrc1[s * 8 + head] + adh));
            float2 hv = __half22float2(*(const __half2*)(g_h1h + s * 64 + c0));
            a0 = fmaf(e, hv.x, a0); a1 = fmaf(e, hv.y, a1);
            sSum += e;
        }
    }
    a0 += b0a + c0a + d0a;
    a1 += b1a + c1a + d1a;
    float inv = 1.f / sSum;
    float o0 = a0 * inv + b1[c0];
    float o1 = a1 * inv + b1[c0 + 1];
    o0 = o0 > 0.f ? o0 : expm1f(o0);
    o1 = o1 > 0.f ? o1 : expm1f(o1);
    __half2 p = __floats2half2_rn(o0, o1);
    *(uint32_t*)(g_hm + w * 64 + c0) = *(uint32_t*)&p;

    float ps = o0 * g_wsd[c0] + o1 * g_wsd[c0 + 1];
    float pd = o0 * g_wsd[64 + c0] + o1 * g_wsd[64 + c0 + 1];
#pragma unroll
    for (int off = 16; off; off >>= 1) {
        ps += __shfl_xor_sync(FULLM, ps, off);
        pd += __shfl_xor_sync(FULLM, pd, off);
    }
    if (lane == 0) { g_asrc2[w] = ps; g_adst2[w] = pd; }
}

// ------------------- GAT conv2 aggregation (4-wide staged consume) -----------
__global__ void __launch_bounds__(256) agg2_kernel()
{
    int w = (blockIdx.x * blockDim.x + threadIdx.x) >> 5;
    int lane = threadIdx.x & 31;
    if (w >= NN) return;
    int c0 = lane * 2;
    int beg = g_rowoff[w], end = g_rowoff[w + 1];
    float adh = g_adst2[w];

    float a0 = 0.f, a1 = 0.f, sSum = 0.f;
    float b0a = 0.f, b1a = 0.f;
    float c0a = 0.f, c1a = 0.f;
    float d0a = 0.f, d1a = 0.f;

    for (int base = beg; base < end; base += 32) {
        int n = end - base;
        int kmax = n < 32 ? n : 32;
        int sl = 0;
        float el = 0.f;
        if (lane < kmax) {
            sl = g_csrsrc[base + lane];
            el = __expf(leaky(g_asrc2[sl] + adh));
        }
        sSum += el;
        int k = 0;
        for (; k + 4 <= kmax; k += 4) {
            int s0 = __shfl_sync(FULLM, sl, k);
            int s1 = __shfl_sync(FULLM, sl, k + 1);
            int s2 = __shfl_sync(FULLM, sl, k + 2);
            int s3 = __shfl_sync(FULLM, sl, k + 3);
            float e0 = __shfl_sync(FULLM, el, k);
            float e1 = __shfl_sync(FULLM, el, k + 1);
            float e2 = __shfl_sync(FULLM, el, k + 2);
            float e3 = __shfl_sync(FULLM, el, k + 3);
            float2 h0 = __half22float2(*(const __half2*)(g_hm + s0 * 64 + c0));
            float2 h1 = __half22float2(*(const __half2*)(g_hm + s1 * 64 + c0));
            float2 h2 = __half22float2(*(const __half2*)(g_hm + s2 * 64 + c0));
            float2 h3 = __half22float2(*(const __half2*)(g_hm + s3 * 64 + c0));
            a0 = fmaf(e0, h0.x, a0);  a1 = fmaf(e0, h0.y, a1);
            b0a = fmaf(e1, h1.x, b0a); b1a = fmaf(e1, h1.y, b1a);
            c0a = fmaf(e2, h2.x, c0a); c1a = fmaf(e2, h2.y, c1a);
            d0a = fmaf(e3, h3.x, d0a); d1a = fmaf(e3, h3.y, d1a);
        }
        for (; k < kmax; k++) {
            int s = __shfl_sync(FULLM, sl, k);
            float e = __shfl_sync(FULLM, el, k);
            float2 hv = __half22float2(*(const __half2*)(g_hm + s * 64 + c0));
            a0 = fmaf(e, hv.x, a0); a1 = fmaf(e, hv.y, a1);
        }
    }
    a0 += b0a + c0a + d0a;
    a1 += b1a + c1a + d1a;
#pragma unroll
    for (int off = 16; off; off >>= 1)
        sSum += __shfl_xor_sync(FULLM, sSum, off);
    float inv = 1.f / sSum;
    __half2 p = __floats2half2_rn(a0 * inv, a1 * inv);
    *(uint32_t*)(g_aggh + w * 64 + c0) = *(uint32_t*)&p;
}

// ------------------- launch --------------------------------------------------
extern "C" void kernel_launch(void* const* d_in, const int* in_sizes, int n_in,
                              void* d_out, int out_size)
{
    (void)in_sizes; (void)n_in; (void)out_size;
    const float* x        = (const float*)d_in[0];
    const int*   ei       = (const int*)d_in[1];
    const float* W_map    = (const float*)d_in[2];
    const float* b_map    = (const float*)d_in[3];
    const float* W1       = (const float*)d_in[4];
    const float* att_src1 = (const float*)d_in[5];
    const float* att_dst1 = (const float*)d_in[6];
    const float* b1       = (const float*)d_in[7];
    const float* W2       = (const float*)d_in[8];
    const float* att_src2 = (const float*)d_in[9];
    const float* att_dst2 = (const float*)d_in[10];
    const float* b2       = (const float*)d_in[11];
    float* out = (float*)d_out;
    const int* src = ei;
    const int* dst = ei + EE;

    __half *p_h1h, *p_aggh;
    float *p_as1, *p_ad1;
    cudaGetSymbolAddress((void**)&p_h1h, g_h1h);
    cudaGetSymbolAddress((void**)&p_aggh, g_aggh);
    cudaGetSymbolAddress((void**)&p_as1, g_asrc1);
    cudaGetSymbolAddress((void**)&p_ad1, g_adst1);

    const int GEMM_BLOCKS = (NN + 127) / 128;
    const int N_BLOCKS    = (NN + 255) / 256;
    const int E_BLOCKS    = (EE + 255) / 256;
    const int WARP_BLOCKS = NN / 8;
    const int SCAN_BLOCKS = (NN + 1023) / 1024;

    cudaStream_t s2 = g_hx.s2;

    prep_w_kernel<<<129, 256>>>(W_map, W1, W2, att_src2, att_dst2);

    cudaEventRecord(g_hx.evF, 0);
    cudaStreamWaitEvent(s2, g_hx.evF, 0);
    init_kernel<<<N_BLOCKS, 256, 0, s2>>>();
    count_kernel<<<E_BLOCKS, 256, 0, s2>>>(dst);

    gemm12_kernel<<<GEMM_BLOCKS, 256, SMEM_G12>>>(
        x, b_map, att_src1, att_dst1, p_h1h, p_as1, p_ad1, NN);

    scan1_kernel<<<SCAN_BLOCKS, 1024, 0, s2>>>();
    scan2_kernel<<<1, 64, 0, s2>>>(SCAN_BLOCKS);
    scan3_kernel<<<SCAN_BLOCKS, 1024, 0, s2>>>();
    scatter_kernel<<<E_BLOCKS, 256, 0, s2>>>(src, dst);
    cudaEventRecord(g_hx.evJ, s2);

    cudaStreamWaitEvent(0, g_hx.evJ, 0);

    agg1_kernel<<<WARP_BLOCKS, 256>>>(b1);
    agg2_kernel<<<WARP_BLOCKS, 256>>>();
    gemm3_kernel<<<GEMM_BLOCKS, 256, SMEM_G3>>>(p_aggh, b2, out, NN);
}